// round 5
// baseline (speedup 1.0000x reference)
#include <cuda_runtime.h>

// Problem constants (fixed by reference hparams)
#define BB     32          // batch
#define NSEG   108         // MAX_NUM_SEG
#define NTOT   3456        // BB*NSEG
#define TX     2560        // MAX_LEN_PAD
#define D4     20          // feature dim / 4 (float4 units)
#define MINSEG 19

// Scratch (no allocations allowed -> __device__ globals)
__device__ int g_offset[NTOT];       // exclusive per-batch cumsum of len_seg
__device__ int g_segbase[NTOT + 1];  // exclusive scan of counts, [NTOT] = total
__device__ int g_rows;               // total / BB

// ---------------------------------------------------------------------------
// shfl-based exclusive warp scan; returns exclusive prefix, sets warp total
// ---------------------------------------------------------------------------
__device__ __forceinline__ int warp_excl(int v, int lane, int& tot) {
    int x = v;
#pragma unroll
    for (int o = 1; o < 32; o <<= 1) {
        int y = __shfl_up_sync(0xffffffffu, x, o);
        if (lane >= o) x += y;
    }
    tot = __shfl_sync(0xffffffffu, x, 31);
    return x - v;
}

// ---------------------------------------------------------------------------
// Fused metadata kernel (single block, 1024 threads):
//   scan #1: global exclusive scan of len_seg -> per-batch offsets
//            (offset[n] = EP[n] - EP[batch_start], batches are contiguous)
//   counts : boundary s* ~= L*scale estimate, verified with exact __fdiv_rn
//            (monotone in s -> 1-3 divisions instead of 7-division bisection)
//   scan #2: global exclusive scan of counts -> g_segbase, g_rows
// ---------------------------------------------------------------------------
__global__ void __launch_bounds__(1024) k_meta(const int* __restrict__ len_seq,
                                               const float* __restrict__ scales_u,
                                               const int* __restrict__ len_seg_raw) {
    __shared__ int sh[NTOT];   // exclusive prefix of len_seg
    __shared__ int shw[33];    // warp partials (+ grand total)
    __shared__ int shls[BB];   // len_seq cache

    const int tid = threadIdx.x, lane = tid & 31, wid = tid >> 5;
    if (tid < BB) shls[tid] = len_seq[tid];

    const int base4 = tid * 4;
    const bool act = tid < NTOT / 4;   // 864 active threads, 4 segments each

    int v0 = 0, v1 = 0, v2 = 0, v3 = 0;
    if (act) {
        v0 = len_seg_raw[base4 + 0] + MINSEG;
        v1 = len_seg_raw[base4 + 1] + MINSEG;
        v2 = len_seg_raw[base4 + 2] + MINSEG;
        v3 = len_seg_raw[base4 + 3] + MINSEG;
    }

    // ---- scan #1: len_seg ----
    {
        int tsum = v0 + v1 + v2 + v3;
        int wtot;
        int ex = warp_excl(tsum, lane, wtot);
        if (lane == 0) shw[wid] = wtot;
        __syncthreads();
        if (wid == 0) {
            int wv = shw[lane], gt;
            shw[lane] = warp_excl(wv, lane, gt);
        }
        __syncthreads();
        int ep = shw[wid] + ex;
        if (act) {
            sh[base4 + 0] = ep;
            sh[base4 + 1] = ep + v0;
            sh[base4 + 2] = ep + v0 + v1;
            sh[base4 + 3] = ep + v0 + v1 + v2;
        }
    }
    __syncthreads();

    // ---- per-segment counts ----
    int c[4] = {0, 0, 0, 0};
    if (act) {
        const int lenv[4] = {v0, v1, v2, v3};
#pragma unroll
        for (int j = 0; j < 4; j++) {
            const int n = base4 + j;
            const int b = n / NSEG;
            const int off = sh[n] - sh[b * NSEG];
            g_offset[n] = off;
            const int L = min(lenv[j] - 1, shls[b] - 1 - off);
            if (L > 0) {
                const float scale = scales_u[n] + 0.5f;
                const float Lf = (float)L;
                // cond(s) := floor(rn(s/scale)) < L, monotone nonincreasing->false
                int s = (int)(Lf * scale);            // seed near the boundary
                if (s > 63) s = 63;
                while (s > 0 && !(floorf(__fdiv_rn((float)s, scale)) < Lf)) s--;
                while (s < 63 && (floorf(__fdiv_rn((float)(s + 1), scale)) < Lf)) s++;
                c[j] = s + 1;                          // cond(0) true since L>0
            }
        }
    }
    __syncthreads();   // done reading shw/sh from scan #1

    // ---- scan #2: counts ----
    {
        int csum = c[0] + c[1] + c[2] + c[3];
        int wtot;
        int ex = warp_excl(csum, lane, wtot);
        if (lane == 0) shw[wid] = wtot;
        __syncthreads();
        if (wid == 0) {
            int wv = shw[lane], gt;
            int wex = warp_excl(wv, lane, gt);
            shw[lane] = wex;
            if (lane == 31) shw[32] = wex + wv;   // grand total
        }
        __syncthreads();
        int cb = shw[wid] + ex;
        if (act) {
            g_segbase[base4 + 0] = cb;
            g_segbase[base4 + 1] = cb + c[0];
            g_segbase[base4 + 2] = cb + c[0] + c[1];
            g_segbase[base4 + 3] = cb + c[0] + c[1] + c[2];
        }
        if (tid == 0) {
            int total = shw[32];
            g_segbase[NTOT] = total;
            g_rows = total / BB;
        }
    }
}

// ---------------------------------------------------------------------------
// Gather: one block = 64 output rows (TX*BB divisible by 64; rows of one block
// never straddle a batch since TX % 64 == 0). Threads 0-63 invert the
// compaction via binary search over g_segbase (L1-resident after wave 1),
// then 640 threads stream 1280 float4 in exactly 2 coalesced iterations.
// ---------------------------------------------------------------------------
__global__ void __launch_bounds__(640) k_gather(const float* __restrict__ x,
                                                const float* __restrict__ scales_u,
                                                float* __restrict__ out) {
    __shared__ int   sh_src[64];   // src batch*TX + frame, -1 = write zeros
    __shared__ float sh_lam[64];

    const int tid = threadIdx.x;
    const int rowbase = blockIdx.x * 64;

    if (tid < 64) {
        const int r = rowbase + tid;
        const int b_out = r / TX;
        const int t = r - b_out * TX;
        const int rows = g_rows;

        int srow = -1;
        float lam = 0.0f;
        if (t < rows) {
            const int p = b_out * rows + t;          // p < total always
            int lo = 0, hi = NTOT;                    // largest n: segbase[n] <= p
            while (hi - lo > 1) {
                const int mid = (lo + hi) >> 1;
                if (g_segbase[mid] <= p) lo = mid;
                else hi = mid;
            }
            const int n = lo;
            const int s = p - g_segbase[n];

            const float v = __fdiv_rn((float)s, scales_u[n] + 0.5f);
            const float fl = floorf(v);
            lam = v - fl;
            int i = (int)(fl + (float)g_offset[n]);  // exact small ints in fp32
            if (i > TX - 2) i = TX - 2;
            if (i < 0) i = 0;
            srow = (n / NSEG) * TX + i;
        }
        sh_src[tid] = srow;
        sh_lam[tid] = lam;
    }
    __syncthreads();

    const float4* __restrict__ x4 = (const float4*)x;
    float4* __restrict__ o4 = (float4*)out;
    const long obase = (long)rowbase * D4;

#pragma unroll
    for (int it = 0; it < 2; it++) {
        const int q = tid + it * 640;                // q < 64*20 = 1280 always
        const int row = q / D4;
        const int d4 = q - row * D4;
        float4 res;
        const int srow = sh_src[row];
        if (srow >= 0) {
            const float lam = sh_lam[row];
            const float om = 1.0f - lam;
            const long sbase = (long)srow * D4 + d4;
            const float4 a = x4[sbase];
            const float4 cc = x4[sbase + D4];
            res.x = om * a.x + lam * cc.x;
            res.y = om * a.y + lam * cc.y;
            res.z = om * a.z + lam * cc.z;
            res.w = om * a.w + lam * cc.w;
        } else {
            res.x = res.y = res.z = res.w = 0.0f;
        }
        o4[obase + q] = res;
    }
}

// ---------------------------------------------------------------------------
extern "C" void kernel_launch(void* const* d_in, const int* in_sizes, int n_in,
                              void* d_out, int out_size) {
    const float* x           = (const float*)d_in[0];  // (32, 2560, 80) f32
    const int*   len_seq     = (const int*)d_in[1];    // (32,) i32
    const float* scales_u    = (const float*)d_in[2];  // (3456,) f32
    const int*   len_seg_raw = (const int*)d_in[3];    // (3456,) i32
    float*       out         = (float*)d_out;          // (32, 2560, 80) f32

    k_meta<<<1, 1024>>>(len_seq, scales_u, len_seg_raw);
    k_gather<<<(BB * TX) / 64, 640>>>(x, scales_u, out);
}

// round 6
// speedup vs baseline: 1.1366x; 1.1366x over previous
#include <cuda_runtime.h>

// Problem constants (fixed by reference hparams)
#define BB     32          // batch
#define NSEG   108         // MAX_NUM_SEG
#define NTOT   3456        // BB*NSEG
#define SS     64          // candidates per segment
#define TX     2560        // MAX_LEN_PAD
#define D4     20          // feature dim / 4 (float4 units)
#define MINSEG 19
#define PMAX   (NTOT * SS) // 221184 max compacted rows

// Scratch (no allocations allowed -> __device__ globals)
__device__ int  g_offset[NTOT];       // exclusive per-batch cumsum of len_seg
__device__ int  g_segbase[NTOT + 1];  // exclusive scan of counts, [NTOT]=total
__device__ int  g_rows;               // total / BB
__device__ int2 g_meta[PMAX];         // per compacted row: {src_row, lam bits}

// ---------------------------------------------------------------------------
// shfl-based exclusive warp scan; returns exclusive prefix, sets warp total
// ---------------------------------------------------------------------------
__device__ __forceinline__ int warp_excl(int v, int lane, int& tot) {
    int x = v;
#pragma unroll
    for (int o = 1; o < 32; o <<= 1) {
        int y = __shfl_up_sync(0xffffffffu, x, o);
        if (lane >= o) x += y;
    }
    tot = __shfl_sync(0xffffffffu, x, 31);
    return x - v;
}

// ---------------------------------------------------------------------------
// Kernel 1 (1 block, 1024 threads): segment offsets, masked counts, scan.
// Count boundary found by estimate (L*scale) + exact __fdiv_rn verification
// so every comparison matches the reference's IEEE floor(s/scale) bit-exact.
// ---------------------------------------------------------------------------
__global__ void __launch_bounds__(1024) k_meta(const int* __restrict__ len_seq,
                                               const float* __restrict__ scales_u,
                                               const int* __restrict__ len_seg_raw) {
    __shared__ int sh[NTOT];   // exclusive prefix of len_seg
    __shared__ int shw[33];    // warp partials (+ grand total)
    __shared__ int shls[BB];   // len_seq cache

    const int tid = threadIdx.x, lane = tid & 31, wid = tid >> 5;
    if (tid < BB) shls[tid] = len_seq[tid];

    const int base4 = tid * 4;
    const bool act = tid < NTOT / 4;   // 864 active threads, 4 segments each

    int v0 = 0, v1 = 0, v2 = 0, v3 = 0;
    if (act) {
        v0 = len_seg_raw[base4 + 0] + MINSEG;
        v1 = len_seg_raw[base4 + 1] + MINSEG;
        v2 = len_seg_raw[base4 + 2] + MINSEG;
        v3 = len_seg_raw[base4 + 3] + MINSEG;
    }

    // ---- scan #1: len_seg -> per-batch offsets ----
    {
        int tsum = v0 + v1 + v2 + v3;
        int wtot;
        int ex = warp_excl(tsum, lane, wtot);
        if (lane == 0) shw[wid] = wtot;
        __syncthreads();
        if (wid == 0) {
            int wv = shw[lane], gt;
            shw[lane] = warp_excl(wv, lane, gt);
        }
        __syncthreads();
        int ep = shw[wid] + ex;
        if (act) {
            sh[base4 + 0] = ep;
            sh[base4 + 1] = ep + v0;
            sh[base4 + 2] = ep + v0 + v1;
            sh[base4 + 3] = ep + v0 + v1 + v2;
        }
    }
    __syncthreads();

    // ---- per-segment counts ----
    int c[4] = {0, 0, 0, 0};
    if (act) {
        const int lenv[4] = {v0, v1, v2, v3};
#pragma unroll
        for (int j = 0; j < 4; j++) {
            const int n = base4 + j;
            const int b = n / NSEG;
            const int off = sh[n] - sh[b * NSEG];
            g_offset[n] = off;
            const int L = min(lenv[j] - 1, shls[b] - 1 - off);
            if (L > 0) {
                const float scale = scales_u[n] + 0.5f;
                const float Lf = (float)L;
                // cond(s) := floor(rn(s/scale)) < L, monotone, cond(0)=true
                int s = (int)(Lf * scale);            // seed near the boundary
                if (s > 63) s = 63;
                while (s > 0 && !(floorf(__fdiv_rn((float)s, scale)) < Lf)) s--;
                while (s < 63 && (floorf(__fdiv_rn((float)(s + 1), scale)) < Lf)) s++;
                c[j] = s + 1;
            }
        }
    }
    __syncthreads();   // shw reuse

    // ---- scan #2: counts -> segbase ----
    {
        int csum = c[0] + c[1] + c[2] + c[3];
        int wtot;
        int ex = warp_excl(csum, lane, wtot);
        if (lane == 0) shw[wid] = wtot;
        __syncthreads();
        if (wid == 0) {
            int wv = shw[lane], gt;
            int wex = warp_excl(wv, lane, gt);
            shw[lane] = wex;
            if (lane == 31) shw[32] = wex + wv;   // grand total
        }
        __syncthreads();
        int cb = shw[wid] + ex;
        if (act) {
            g_segbase[base4 + 0] = cb;
            g_segbase[base4 + 1] = cb + c[0];
            g_segbase[base4 + 2] = cb + c[0] + c[1];
            g_segbase[base4 + 3] = cb + c[0] + c[1] + c[2];
        }
        if (tid == 0) {
            int total = shw[32];
            g_segbase[NTOT] = total;
            g_rows = total / BB;
        }
    }
}

// ---------------------------------------------------------------------------
// Kernel 2: per-compacted-row metadata scatter. One warp per segment — the
// segment KNOWS its destination range [segbase[n], segbase[n]+cnt), so no
// search anywhere. Writes {src_row, lambda} coalesced (int2).
// ---------------------------------------------------------------------------
__global__ void __launch_bounds__(256) k_rowmeta(const float* __restrict__ scales_u) {
    const int n = (blockIdx.x * 256 + threadIdx.x) >> 5;   // global warp id
    if (n >= NTOT) return;
    const int lane = threadIdx.x & 31;

    const int base = g_segbase[n];
    const int cnt  = g_segbase[n + 1] - base;
    if (cnt == 0) return;

    const int   off   = g_offset[n];
    const int   bTX   = (n / NSEG) * TX;
    const float scale = scales_u[n] + 0.5f;

#pragma unroll
    for (int s = lane; s < cnt; s += 32) {   // cnt <= 64 -> at most 2 iters
        const float v  = __fdiv_rn((float)s, scale);
        const float fl = floorf(v);
        const float lam = v - fl;
        int i = (int)fl + off;               // exact small ints
        if (i > TX - 2) i = TX - 2;
        if (i < 0) i = 0;
        g_meta[base + s] = make_int2(bTX + i, __float_as_int(lam));
    }
}

// ---------------------------------------------------------------------------
// Kernel 3: barrier-free flat gather. One thread = one output float4.
// meta[p] is broadcast across the 20 threads of a row via L1; x reads are
// coalesced per row; stores are perfectly coalesced. No smem, no syncs —
// latency hidden purely by thread parallelism.
// ---------------------------------------------------------------------------
__global__ void __launch_bounds__(256) k_gather(const float* __restrict__ x,
                                                float* __restrict__ out) {
    const unsigned gid = blockIdx.x * 256u + threadIdx.x;  // < 32*2560*20
    const unsigned row = gid / D4;
    const unsigned d4  = gid - row * D4;
    const unsigned b   = row / TX;
    const unsigned t   = row - b * TX;

    float4 res = make_float4(0.f, 0.f, 0.f, 0.f);
    const int rows = g_rows;
    if ((int)t < rows) {
        const int p = (int)b * rows + (int)t;
        const int2 m = g_meta[p];
        const float lam = __int_as_float(m.y);
        const float om  = 1.0f - lam;
        const float4* __restrict__ x4 = (const float4*)x;
        const long sbase = (long)m.x * D4 + d4;
        const float4 a = x4[sbase];
        const float4 c = x4[sbase + D4];
        res.x = om * a.x + lam * c.x;
        res.y = om * a.y + lam * c.y;
        res.z = om * a.z + lam * c.z;
        res.w = om * a.w + lam * c.w;
    }
    ((float4*)out)[gid] = res;
}

// ---------------------------------------------------------------------------
extern "C" void kernel_launch(void* const* d_in, const int* in_sizes, int n_in,
                              void* d_out, int out_size) {
    const float* x           = (const float*)d_in[0];  // (32, 2560, 80) f32
    const int*   len_seq     = (const int*)d_in[1];    // (32,) i32
    const float* scales_u    = (const float*)d_in[2];  // (3456,) f32
    const int*   len_seg_raw = (const int*)d_in[3];    // (3456,) i32
    float*       out         = (float*)d_out;          // (32, 2560, 80) f32

    k_meta<<<1, 1024>>>(len_seq, scales_u, len_seg_raw);
    k_rowmeta<<<(NTOT * 32 + 255) / 256, 256>>>(scales_u);
    k_gather<<<(BB * TX * D4) / 256, 256>>>(x, out);
}

// round 7
// speedup vs baseline: 1.2718x; 1.1189x over previous
#include <cuda_runtime.h>

// Problem constants (fixed by reference hparams)
#define BB     32          // batch
#define NSEG   108         // MAX_NUM_SEG
#define NTOT   3456        // BB*NSEG
#define SS     64          // candidates per segment
#define TX     2560        // MAX_LEN_PAD
#define D4     20          // feature dim / 4 (float4 units)
#define MINSEG 19
#define PMAX   (NTOT * SS) // 221184 max compacted rows

// Scratch (no allocations allowed -> __device__ globals)
__device__ int  g_offset[NTOT];    // exclusive per-batch cumsum of len_seg
__device__ int  g_locbase[NTOT];   // within-batch exclusive scan of counts
__device__ int  g_cnt[NTOT];       // per-segment masked count
__device__ int  g_btot[BB];        // per-batch count total
__device__ int  g_rows;            // total / BB
__device__ int2 g_meta[PMAX];      // per compacted row: {src_row, lam bits}

// ---------------------------------------------------------------------------
// shfl exclusive warp scan; returns exclusive prefix, sets warp total
// ---------------------------------------------------------------------------
__device__ __forceinline__ int warp_excl(int v, int lane, int& tot) {
    int x = v;
#pragma unroll
    for (int o = 1; o < 32; o <<= 1) {
        int y = __shfl_up_sync(0xffffffffu, x, o);
        if (lane >= o) x += y;
    }
    tot = __shfl_sync(0xffffffffu, x, 31);
    return x - v;
}

// block-wide exclusive scan for 128 threads (4 warps) via smem combine
__device__ __forceinline__ int block_excl_128(int v, int tid, int* warp_part,
                                              int* out_total) {
    const int lane = tid & 31, wid = tid >> 5;
    int wtot;
    int ex = warp_excl(v, lane, wtot);
    if (lane == 0) warp_part[wid] = wtot;
    __syncthreads();
    int wbase = 0;
#pragma unroll
    for (int k = 0; k < 4; k++) {
        int p = warp_part[k];
        if (k < wid) wbase += p;
        if (k == 3 && out_total) *out_total = wbase + ((wid == 3) ? 0 : 0);
    }
    // total = sum of all 4 partials (recompute cleanly)
    if (out_total) {
        int t = warp_part[0] + warp_part[1] + warp_part[2] + warp_part[3];
        *out_total = t;
    }
    __syncthreads();   // allow warp_part reuse by caller
    return wbase + ex;
}

// ---------------------------------------------------------------------------
// Kernel 1: 32 blocks (one per batch) x 128 threads.
//   - exclusive scan of 108 len_seg -> per-segment offsets
//   - per-segment masked count (estimate L*scale + exact __fdiv_rn verify,
//     bit-exact against the reference's IEEE floor(s/scale))
//   - exclusive scan of counts -> local segbase; batch total -> g_btot
// ---------------------------------------------------------------------------
__global__ void __launch_bounds__(128) k_seg(const int* __restrict__ len_seq,
                                             const float* __restrict__ scales_u,
                                             const int* __restrict__ len_seg_raw) {
    __shared__ int warp_part[4];

    const int b = blockIdx.x;
    const int tid = threadIdx.x;
    const bool act = tid < NSEG;

    int len = 0;
    if (act) len = len_seg_raw[b * NSEG + tid] + MINSEG;

    int tot;
    const int off = block_excl_128(len, tid, warp_part, &tot);

    int cnt = 0;
    if (act) {
        g_offset[b * NSEG + tid] = off;
        const int L = min(len - 1, len_seq[b] - 1 - off);
        if (L > 0) {
            const float scale = scales_u[b * NSEG + tid] + 0.5f;
            const float Lf = (float)L;
            // cond(s) := floor(rn(s/scale)) < L; monotone, cond(0)=true
            int s = (int)(Lf * scale);             // seed near the boundary
            if (s > 63) s = 63;
            while (s > 0 && !(floorf(__fdiv_rn((float)s, scale)) < Lf)) s--;
            while (s < 63 && (floorf(__fdiv_rn((float)(s + 1), scale)) < Lf)) s++;
            cnt = s + 1;
        }
        g_cnt[b * NSEG + tid] = cnt;
    }
    __syncthreads();   // warp_part reuse

    int ctot;
    const int lbase = block_excl_128(cnt, tid, warp_part, &ctot);
    if (act) g_locbase[b * NSEG + tid] = lbase;
    if (tid == 0) g_btot[b] = ctot;
}

// ---------------------------------------------------------------------------
// Kernel 2: per-compacted-row metadata scatter. 432 blocks x 256 threads,
// one warp per segment. Prologue: warp 0 scans the 32 batch totals -> batch
// bases (smem); block 0 also publishes g_rows. Then each segment scatters its
// cnt<=64 rows ({src_row, lambda}) to its KNOWN destination range - no search.
// ---------------------------------------------------------------------------
__global__ void __launch_bounds__(256) k_rowmeta(const float* __restrict__ scales_u) {
    __shared__ int sbb[33];   // batch bases + grand total

    const int tid = threadIdx.x;
    if (tid < 32) {
        int v = g_btot[tid];
        int t;
        int ex = warp_excl(v, tid, t);
        sbb[tid] = ex;
        if (tid == 31) sbb[32] = t;
    }
    __syncthreads();
    if (blockIdx.x == 0 && tid == 0) g_rows = sbb[32] / BB;

    const int n = blockIdx.x * 8 + (tid >> 5);   // 8 warps -> 8 segments
    const int lane = tid & 31;

    const int cnt = g_cnt[n];
    if (cnt == 0) return;
    const int b = n / NSEG;
    const int base = sbb[b] + g_locbase[n];

    const int   off   = g_offset[n];
    const int   bTX   = b * TX;
    const float scale = scales_u[n] + 0.5f;

#pragma unroll
    for (int s = lane; s < cnt; s += 32) {   // cnt <= 64 -> at most 2 iters
        const float v  = __fdiv_rn((float)s, scale);
        const float fl = floorf(v);
        const float lam = v - fl;
        int i = (int)fl + off;               // exact small ints
        if (i > TX - 2) i = TX - 2;
        if (i < 0) i = 0;
        g_meta[base + s] = make_int2(bTX + i, __float_as_int(lam));
    }
}

// ---------------------------------------------------------------------------
// Kernel 3: barrier-free flat gather. One thread = one output float4.
// meta[p] broadcast across the 20 threads of a row via L1; x reads coalesced
// per row; stores perfectly coalesced. No smem, no syncs.
// ---------------------------------------------------------------------------
__global__ void __launch_bounds__(256) k_gather(const float* __restrict__ x,
                                                float* __restrict__ out) {
    const unsigned gid = blockIdx.x * 256u + threadIdx.x;  // < 32*2560*20
    const unsigned row = gid / D4;
    const unsigned d4  = gid - row * D4;
    const unsigned b   = row / TX;
    const unsigned t   = row - b * TX;

    float4 res = make_float4(0.f, 0.f, 0.f, 0.f);
    const int rows = g_rows;
    if ((int)t < rows) {
        const int p = (int)b * rows + (int)t;
        const int2 m = g_meta[p];
        const float lam = __int_as_float(m.y);
        const float om  = 1.0f - lam;
        const float4* __restrict__ x4 = (const float4*)x;
        const long sbase = (long)m.x * D4 + d4;
        const float4 a = x4[sbase];
        const float4 c = x4[sbase + D4];
        res.x = om * a.x + lam * c.x;
        res.y = om * a.y + lam * c.y;
        res.z = om * a.z + lam * c.z;
        res.w = om * a.w + lam * c.w;
    }
    ((float4*)out)[gid] = res;
}

// ---------------------------------------------------------------------------
extern "C" void kernel_launch(void* const* d_in, const int* in_sizes, int n_in,
                              void* d_out, int out_size) {
    const float* x           = (const float*)d_in[0];  // (32, 2560, 80) f32
    const int*   len_seq     = (const int*)d_in[1];    // (32,) i32
    const float* scales_u    = (const float*)d_in[2];  // (3456,) f32
    const int*   len_seg_raw = (const int*)d_in[3];    // (3456,) i32
    float*       out         = (float*)d_out;          // (32, 2560, 80) f32

    k_seg<<<BB, 128>>>(len_seq, scales_u, len_seg_raw);
    k_rowmeta<<<NTOT / 8, 256>>>(scales_u);
    k_gather<<<(BB * TX * D4) / 256, 256>>>(x, out);
}

// round 8
// speedup vs baseline: 1.2937x; 1.0173x over previous
#include <cuda_runtime.h>

// Problem constants (fixed by reference hparams)
#define BB     32          // batch
#define NSEG   108         // MAX_NUM_SEG
#define NTOT   3456        // BB*NSEG
#define SS     64          // candidates per segment
#define TX     2560        // MAX_LEN_PAD
#define D4     20          // feature dim / 4 (float4 units)
#define MINSEG 19
#define PMAX   (NTOT * SS) // 221184 max compacted rows

// Scratch (no allocations allowed -> __device__ globals)
__device__ int  g_offset[NTOT];    // exclusive per-batch cumsum of len_seg
__device__ int  g_locbase[NTOT];   // within-batch exclusive scan of counts
__device__ int  g_cnt[NTOT];       // per-segment masked count
__device__ int  g_btot[BB];        // per-batch count total
__device__ int  g_rows;            // total / BB
__device__ int2 g_meta[PMAX];      // per compacted row: {src_row, lam bits}

// ---------------------------------------------------------------------------
// shfl exclusive warp scan; returns exclusive prefix, sets warp total
// ---------------------------------------------------------------------------
__device__ __forceinline__ int warp_excl(int v, int lane, int& tot) {
    int x = v;
#pragma unroll
    for (int o = 1; o < 32; o <<= 1) {
        int y = __shfl_up_sync(0xffffffffu, x, o);
        if (lane >= o) x += y;
    }
    tot = __shfl_sync(0xffffffffu, x, 31);
    return x - v;
}

// Masked count for one segment: #{ s in [0,64) : floor(rn(s/scale)) < L }.
// Estimate seed + exact __fdiv_rn verification -> bit-exact vs reference.
__device__ __forceinline__ int seg_cnt(int len, int lseq, int off, float su) {
    const int L = min(len - 1, lseq - 1 - off);
    if (L <= 0) return 0;
    const float scale = su + 0.5f;
    const float Lf = (float)L;
    int s = (int)(Lf * scale);             // seed near the boundary
    if (s > 63) s = 63;
    while (s > 0 && !(floorf(__fdiv_rn((float)s, scale)) < Lf)) s--;
    while (s < 63 && (floorf(__fdiv_rn((float)(s + 1), scale)) < Lf)) s++;
    return s + 1;                          // cond(0) true since L>0
}

// ---------------------------------------------------------------------------
// Kernel 1: one WARP per batch, zero barriers. 27 lanes x 4 segments (=108),
// vectorized int4/float4 loads, shfl scans only. All inputs issued up front
// so the cold DRAM latencies overlap.
// ---------------------------------------------------------------------------
__global__ void __launch_bounds__(32) k_seg(const int* __restrict__ len_seq,
                                            const float* __restrict__ scales_u,
                                            const int* __restrict__ len_seg_raw) {
    const int b = blockIdx.x;
    const int lane = threadIdx.x;
    const bool act = lane < NSEG / 4;      // 27 active lanes

    // issue all loads first (independent -> MLP hides DRAM latency)
    int4 lr = make_int4(-MINSEG, -MINSEG, -MINSEG, -MINSEG);
    float4 sc = make_float4(1.f, 1.f, 1.f, 1.f);
    const int vidx = b * (NSEG / 4) + lane;
    if (act) {
        lr = ((const int4*)len_seg_raw)[vidx];
        sc = ((const float4*)scales_u)[vidx];
    }
    const int lseq = len_seq[b];

    const int l0 = lr.x + MINSEG, l1 = lr.y + MINSEG;
    const int l2 = lr.z + MINSEG, l3 = lr.w + MINSEG;

    // ---- scan #1: len_seg -> offsets (shfl only) ----
    int tot;
    const int ex = warp_excl(l0 + l1 + l2 + l3, lane, tot);
    const int o0 = ex, o1 = ex + l0, o2 = o1 + l1, o3 = o2 + l2;

    // ---- per-segment counts (ILP across the 4 segments) ----
    const int c0 = seg_cnt(l0, lseq, o0, sc.x);
    const int c1 = seg_cnt(l1, lseq, o1, sc.y);
    const int c2 = seg_cnt(l2, lseq, o2, sc.z);
    const int c3 = seg_cnt(l3, lseq, o3, sc.w);

    // ---- scan #2: counts -> local bases + batch total ----
    int ctot;
    const int cex = warp_excl(c0 + c1 + c2 + c3, lane, ctot);

    if (act) {
        ((int4*)g_offset)[vidx]  = make_int4(o0, o1, o2, o3);
        ((int4*)g_cnt)[vidx]     = make_int4(c0, c1, c2, c3);
        ((int4*)g_locbase)[vidx] = make_int4(cex, cex + c0, cex + c0 + c1,
                                             cex + c0 + c1 + c2);
    }
    if (lane == 0) g_btot[b] = ctot;
}

// ---------------------------------------------------------------------------
// Kernel 2: per-compacted-row metadata scatter. 432 blocks x 256 threads,
// one warp per segment. Prologue: warp 0 scans the 32 batch totals -> batch
// bases (smem); block 0 publishes g_rows. Then each segment scatters its
// cnt<=64 rows ({src_row, lambda}) to its KNOWN destination range - no search.
// ---------------------------------------------------------------------------
__global__ void __launch_bounds__(256) k_rowmeta(const float* __restrict__ scales_u) {
    __shared__ int sbb[33];   // batch bases + grand total

    const int tid = threadIdx.x;
    if (tid < 32) {
        int v = g_btot[tid];
        int t;
        int ex = warp_excl(v, tid, t);
        sbb[tid] = ex;
        if (tid == 31) sbb[32] = t;
    }
    __syncthreads();
    if (blockIdx.x == 0 && tid == 0) g_rows = sbb[32] / BB;

    const int n = blockIdx.x * 8 + (tid >> 5);   // 8 warps -> 8 segments
    const int lane = tid & 31;

    const int cnt = g_cnt[n];
    if (cnt == 0) return;
    const int b = n / NSEG;
    const int base = sbb[b] + g_locbase[n];

    const int   off   = g_offset[n];
    const int   bTX   = b * TX;
    const float scale = scales_u[n] + 0.5f;

#pragma unroll
    for (int s = lane; s < cnt; s += 32) {   // cnt <= 64 -> at most 2 iters
        const float v  = __fdiv_rn((float)s, scale);
        const float fl = floorf(v);
        const float lam = v - fl;
        int i = (int)fl + off;               // exact small ints
        if (i > TX - 2) i = TX - 2;
        if (i < 0) i = 0;
        g_meta[base + s] = make_int2(bTX + i, __float_as_int(lam));
    }
}

// ---------------------------------------------------------------------------
// Kernel 3: barrier-free flat gather. One thread = one output float4.
// meta[p] broadcast across the 20 threads of a row via L1; x reads coalesced
// per row; stores perfectly coalesced. No smem, no syncs.
// ---------------------------------------------------------------------------
__global__ void __launch_bounds__(256) k_gather(const float* __restrict__ x,
                                                float* __restrict__ out) {
    const unsigned gid = blockIdx.x * 256u + threadIdx.x;  // < 32*2560*20
    const unsigned row = gid / D4;
    const unsigned d4  = gid - row * D4;
    const unsigned b   = row / TX;
    const unsigned t   = row - b * TX;

    float4 res = make_float4(0.f, 0.f, 0.f, 0.f);
    const int rows = g_rows;
    if ((int)t < rows) {
        const int p = (int)b * rows + (int)t;
        const int2 m = g_meta[p];
        const float lam = __int_as_float(m.y);
        const float om  = 1.0f - lam;
        const float4* __restrict__ x4 = (const float4*)x;
        const long sbase = (long)m.x * D4 + d4;
        const float4 a = x4[sbase];
        const float4 c = x4[sbase + D4];
        res.x = om * a.x + lam * c.x;
        res.y = om * a.y + lam * c.y;
        res.z = om * a.z + lam * c.z;
        res.w = om * a.w + lam * c.w;
    }
    ((float4*)out)[gid] = res;
}

// ---------------------------------------------------------------------------
extern "C" void kernel_launch(void* const* d_in, const int* in_sizes, int n_in,
                              void* d_out, int out_size) {
    const float* x           = (const float*)d_in[0];  // (32, 2560, 80) f32
    const int*   len_seq     = (const int*)d_in[1];    // (32,) i32
    const float* scales_u    = (const float*)d_in[2];  // (3456,) f32
    const int*   len_seg_raw = (const int*)d_in[3];    // (3456,) i32
    float*       out         = (float*)d_out;          // (32, 2560, 80) f32

    k_seg<<<BB, 32>>>(len_seq, scales_u, len_seg_raw);
    k_rowmeta<<<NTOT / 8, 256>>>(scales_u);
    k_gather<<<(BB * TX * D4) / 256, 256>>>(x, out);
}